// round 7
// baseline (speedup 1.0000x reference)
#include <cuda_runtime.h>
#include <cstdint>

// SOM forward: x[128,256] f32, weights[64,64,256] f32
// out = [ bmus(128*2 floats) , diffs(128*64*64*256 floats) ]
//
// R7: store-path fix. STG.128 through L1tex was co-saturated with DRAM
// (~70%/~69%). Diffs are now staged in SMEM and written with TMA 1D bulk
// stores (cp.async.bulk.global.shared::cta) -> bypasses L1tex + per-STG
// LSU issue cost. Double-buffered 16KB chunks. Block = (batch b, 128
// contiguous neurons) -> 128KB contiguous output per block. d2 in regs,
// deferred reductions, one atomic per warp. Single launch; last-block
// epilogue writes bmus and re-arms globals (graph-replay deterministic).

#define B 128
#define D 256
#define MAPM 4096                  // 64*64 neurons
#define THREADS 512                // 16 warps
#define M_PER_BLOCK 128
#define CHUNK_M 16                 // m's per chunk == warps per block
#define NCHUNKS (M_PER_BLOCK / CHUNK_M)           // 8
#define MBLOCKS (MAPM / M_PER_BLOCK)              // 32
#define NBLOCKS (B * MBLOCKS)                     // 4096
#define CHUNK_BYTES (CHUNK_M * D * 4)             // 16384

__device__ unsigned long long g_best[B];   // zero-init; holds ~min_key
__device__ unsigned int g_done;            // zero-init ticket

__global__ __launch_bounds__(THREADS) void som_fused_kernel(
    const float* __restrict__ x,
    const float* __restrict__ w,
    float* __restrict__ out)   // out = [bmus | diffs]
{
    __shared__ float4 sbuf[2][CHUNK_M * D / 4];   // 2 x 16KB

    float* __restrict__ diffs = out + B * 2;

    const int tid  = threadIdx.x;
    const int warp = tid >> 5;          // 0..15
    const int lane = tid & 31;
    const int b    = blockIdx.x >> 5;   // 0..127
    const int mb   = blockIdx.x & 31;   // 0..31
    const int m_base = mb * M_PER_BLOCK;

    // x[b] in registers, reused for all 128 neurons of this block
    const float4* __restrict__ xv = reinterpret_cast<const float4*>(x + (size_t)b * D);
    const float4 xa0 = xv[lane];
    const float4 xa1 = xv[32 + lane];

    float acc[NCHUNKS];

    const size_t out_base_f = ((size_t)b * MAPM + m_base) * D;

#pragma unroll
    for (int c = 0; c < NCHUNKS; c++) {
        const int buf = c & 1;

        if (c >= 2) {
            // buffer reuse: wait until TMA has finished READING chunk c-2
            if (tid == 0)
                asm volatile("cp.async.bulk.wait_group.read 1;" ::: "memory");
            __syncthreads();
        }

        // this warp's neuron for this chunk
        const int m = m_base + c * CHUNK_M + warp;
        const float4* __restrict__ wv =
            reinterpret_cast<const float4*>(w + (size_t)m * D);
        const float4 wa0 = wv[lane];
        const float4 wa1 = wv[32 + lane];

        float4 d0, d1;
        d0.x = xa0.x - wa0.x;  d0.y = xa0.y - wa0.y;
        d0.z = xa0.z - wa0.z;  d0.w = xa0.w - wa0.w;
        d1.x = xa1.x - wa1.x;  d1.y = xa1.y - wa1.y;
        d1.z = xa1.z - wa1.z;  d1.w = xa1.w - wa1.w;

        // stage into SMEM (conflict-free contiguous STS.128)
        sbuf[buf][warp * 64 + lane]      = d0;
        sbuf[buf][warp * 64 + 32 + lane] = d1;

        float a;
        a = d0.x * d0.x;
        a = fmaf(d0.y, d0.y, a);
        a = fmaf(d0.z, d0.z, a);
        a = fmaf(d0.w, d0.w, a);
        a = fmaf(d1.x, d1.x, a);
        a = fmaf(d1.y, d1.y, a);
        a = fmaf(d1.z, d1.z, a);
        a = fmaf(d1.w, d1.w, a);
        acc[c] = a;

        __syncthreads();   // all STS of this chunk visible

        if (tid == 0) {
            // order generic-proxy STS before async-proxy TMA read
            asm volatile("fence.proxy.async.shared::cta;" ::: "memory");
            const float* gdst = diffs + out_base_f + (size_t)c * CHUNK_M * D;
            unsigned int saddr =
                (unsigned int)__cvta_generic_to_shared(&sbuf[buf][0]);
            asm volatile(
                "cp.async.bulk.global.shared::cta.bulk_group [%0], [%1], %2;"
                :: "l"(gdst), "r"(saddr), "r"((unsigned int)CHUNK_BYTES)
                : "memory");
            asm volatile("cp.async.bulk.commit_group;" ::: "memory");
        }
    }

    // 8 independent warp reductions, interleaved
#pragma unroll
    for (int off = 16; off; off >>= 1) {
#pragma unroll
        for (int c = 0; c < NCHUNKS; c++)
            acc[c] += __shfl_down_sync(0xffffffffu, acc[c], off);
    }

    if (lane == 0) {
        // local argmin over this warp's 8 neurons, then ONE atomic.
        // key = (d2_bits << 32) | m: u64 min == argmin, lowest-m ties.
        unsigned long long best = 0xFFFFFFFFFFFFFFFFULL;
#pragma unroll
        for (int c = 0; c < NCHUNKS; c++) {
            unsigned long long key =
                ((unsigned long long)__float_as_uint(acc[c]) << 32) |
                (unsigned int)(m_base + c * CHUNK_M + warp);
            best = (key < best) ? key : best;
        }
        atomicMax(&g_best[b], ~best);   // min(key) == max(~key); zero-init safe
    }

    // drain all outstanding TMA stores before exit
    if (tid == 0)
        asm volatile("cp.async.bulk.wait_group 0;" ::: "memory");

    // ---- last-block epilogue: write bmus, re-arm globals for next replay ----
    __shared__ unsigned int s_last;
    __syncthreads();
    if (tid == 0) {
        __threadfence();  // publish this block's g_best update
        unsigned int ticket = atomicAdd(&g_done, 1);
        s_last = (ticket == NBLOCKS - 1) ? 1u : 0u;
    }
    __syncthreads();
    if (s_last) {
        __threadfence();  // acquire all other blocks' g_best updates
        if (tid < B) {
            unsigned long long v = ~g_best[tid];
            unsigned int mm = (unsigned int)(v & 0xFFFFFFFFu);
            out[tid * 2 + 0] = (float)(mm >> 6);   // row
            out[tid * 2 + 1] = (float)(mm & 63);   // col
            g_best[tid] = 0ULL;                    // re-arm
        }
        if (tid == 0) g_done = 0;                  // re-arm ticket
    }
}

extern "C" void kernel_launch(void* const* d_in, const int* in_sizes, int n_in,
                              void* d_out, int out_size) {
    const float* x = (const float*)d_in[0];
    const float* w = (const float*)d_in[1];
    som_fused_kernel<<<NBLOCKS, THREADS>>>(x, w, (float*)d_out);
}

// round 8
// speedup vs baseline: 1.0694x; 1.0694x over previous
#include <cuda_runtime.h>
#include <cstdint>

// SOM forward: x[128,256] f32, weights[64,64,256] f32
// out = [ bmus(128*2 floats) , diffs(128*64*64*256 floats) ]
//
// R8: LTS-traffic fix. R5 core (warp = 16 contiguous m, 16KB contiguous
// streaming stores, per-lane acc[16], deferred reductions, 1 atomic/warp)
// with a reshaped block: 1024 threads = 4 batch-groups x 8 warps, all
// reading the SAME 128KB w slab -> w re-reads hit L1 instead of L2,
// cutting LTS read traffic 4x (L2 crossbar was co-saturated with DRAM).
// Single launch; last-block epilogue writes bmus + re-arms globals.

#define B 128
#define D 256
#define MAPM 4096                  // 64*64 neurons
#define THREADS 1024               // 32 warps
#define B_PER_BLOCK 4
#define M_PER_WARP 16
#define WARPS_PER_BGROUP 8
#define M_PER_BLOCK (M_PER_WARP * WARPS_PER_BGROUP)  // 128
#define MBLOCKS (MAPM / M_PER_BLOCK)                  // 32
#define NBLOCKS ((B / B_PER_BLOCK) * MBLOCKS)         // 1024

__device__ unsigned long long g_best[B];   // zero-init; holds ~min_key
__device__ unsigned int g_done;            // zero-init ticket

__global__ __launch_bounds__(THREADS, 1) void som_fused_kernel(
    const float* __restrict__ x,
    const float* __restrict__ w,
    float* __restrict__ out)   // out = [bmus | diffs]
{
    float* __restrict__ diffs = out + B * 2;

    const int warp = threadIdx.x >> 5;          // 0..31
    const int lane = threadIdx.x & 31;
    const int bq   = warp >> 3;                 // 0..3 batch within block
    const int mc   = warp & 7;                  // 0..7 m-chunk within block

    const int bb   = blockIdx.x >> 5;           // 0..31 batch-group
    const int mb   = blockIdx.x & 31;           // 0..31 m-block
    const int b    = bb * B_PER_BLOCK + bq;
    const int m0   = mb * M_PER_BLOCK + mc * M_PER_WARP;

    // x[b] in registers (reused for all 16 neurons)
    const float4* __restrict__ xv = reinterpret_cast<const float4*>(x + (size_t)b * D);
    const float4 xa0 = xv[lane];
    const float4 xa1 = xv[32 + lane];

    const float4* __restrict__ wv =
        reinterpret_cast<const float4*>(w + (size_t)m0 * D);
    float4* __restrict__ ov =
        reinterpret_cast<float4*>(diffs + ((size_t)b * MAPM + m0) * D);

    float acc[M_PER_WARP];

    // 1-deep software pipeline on the w row (L1-hit after first batch-group)
    float4 wn0 = wv[lane];
    float4 wn1 = wv[32 + lane];

#pragma unroll
    for (int i = 0; i < M_PER_WARP; i++) {
        float4 wa0 = wn0, wa1 = wn1;
        if (i + 1 < M_PER_WARP) {
            wn0 = wv[(i + 1) * 64 + lane];       // contiguous next w row
            wn1 = wv[(i + 1) * 64 + 32 + lane];
        }

        float4 d0, d1;
        d0.x = xa0.x - wa0.x;  d0.y = xa0.y - wa0.y;
        d0.z = xa0.z - wa0.z;  d0.w = xa0.w - wa0.w;
        d1.x = xa1.x - wa1.x;  d1.y = xa1.y - wa1.y;
        d1.z = xa1.z - wa1.z;  d1.w = xa1.w - wa1.w;

        // contiguous streaming stores: warp covers 16KB
        __stcs(ov + i * 64 + lane,      d0);
        __stcs(ov + i * 64 + 32 + lane, d1);

        float a;
        a = d0.x * d0.x;
        a = fmaf(d0.y, d0.y, a);
        a = fmaf(d0.z, d0.z, a);
        a = fmaf(d0.w, d0.w, a);
        a = fmaf(d1.x, d1.x, a);
        a = fmaf(d1.y, d1.y, a);
        a = fmaf(d1.z, d1.z, a);
        a = fmaf(d1.w, d1.w, a);
        acc[i] = a;                    // per-lane partial; no cross-lane ops
    }

    // 16 independent warp reductions, interleaved (latency overlapped)
#pragma unroll
    for (int off = 16; off; off >>= 1) {
#pragma unroll
        for (int i = 0; i < M_PER_WARP; i++)
            acc[i] += __shfl_down_sync(0xffffffffu, acc[i], off);
    }

    if (lane == 0) {
        // local argmin over this warp's 16 neurons, then ONE global atomic.
        // key = (d2_bits << 32) | m: u64 min == argmin with lowest-m ties.
        unsigned long long best = 0xFFFFFFFFFFFFFFFFULL;
#pragma unroll
        for (int i = 0; i < M_PER_WARP; i++) {
            unsigned long long key =
                ((unsigned long long)__float_as_uint(acc[i]) << 32) |
                (unsigned int)(m0 + i);
            best = (key < best) ? key : best;
        }
        atomicMax(&g_best[b], ~best);   // min(key) == max(~key); zero-init safe
    }

    // ---- last-block epilogue: write bmus, re-arm globals for next replay ----
    __shared__ unsigned int s_last;
    __syncthreads();
    if (threadIdx.x == 0) {
        __threadfence();  // publish this block's g_best updates
        unsigned int ticket = atomicAdd(&g_done, 1);
        s_last = (ticket == NBLOCKS - 1) ? 1u : 0u;
    }
    __syncthreads();
    if (s_last) {
        __threadfence();  // acquire all other blocks' g_best updates
        if (threadIdx.x < B) {
            unsigned long long v = ~g_best[threadIdx.x];
            unsigned int mm = (unsigned int)(v & 0xFFFFFFFFu);
            out[threadIdx.x * 2 + 0] = (float)(mm >> 6);   // row
            out[threadIdx.x * 2 + 1] = (float)(mm & 63);   // col
            g_best[threadIdx.x] = 0ULL;                    // re-arm
        }
        if (threadIdx.x == 0) g_done = 0;                  // re-arm ticket
    }
}

extern "C" void kernel_launch(void* const* d_in, const int* in_sizes, int n_in,
                              void* d_out, int out_size) {
    const float* x = (const float*)d_in[0];
    const float* w = (const float*)d_in[1];
    som_fused_kernel<<<NBLOCKS, THREADS>>>(x, w, (float*)d_out);
}

// round 9
// speedup vs baseline: 1.0697x; 1.0004x over previous
#include <cuda_runtime.h>
#include <cstdint>

// SOM forward: x[128,256] f32, weights[64,64,256] f32
// out = [ bmus(128*2 floats) , diffs(128*64*64*256 floats) ]
//
// R9: persistence fix. R5 inner loop verbatim (warp = 16 contiguous m,
// 16KB contiguous streaming stores, per-lane acc[16], deferred interleaved
// reductions, 1 atomic/warp) but launched as a SINGLE WAVE: 740 blocks
// (148 SMs x 5 resident), each looping over a contiguous range of the
// 4096 (b, m-block) tiles. Removes 5.5 wave transitions + per-wave store
// pipeline drain; contiguous tile ranges give each block up to 768KB of
// contiguous writes. Last-block epilogue writes bmus + re-arms globals.

#define B 128
#define D 256
#define MAPM 4096                 // 64*64 neurons
#define M_PER_WARP 16
#define WARPS_PER_BLOCK 8
#define M_PER_BLOCK (M_PER_WARP * WARPS_PER_BLOCK)  // 128
#define MBLOCKS (MAPM / M_PER_BLOCK)                // 32
#define NTILES (B * MBLOCKS)                        // 4096 tiles
#define NBLOCKS 740                                 // 148 SMs x 5 resident

__device__ unsigned long long g_best[B];   // zero-init; holds ~min_key
__device__ unsigned int g_done;            // zero-init ticket

__global__ __launch_bounds__(256, 5) void som_fused_kernel(
    const float* __restrict__ x,
    const float* __restrict__ w,
    float* __restrict__ out)   // out = [bmus | diffs]
{
    float* __restrict__ diffs = out + B * 2;

    const int warp = threadIdx.x >> 5;
    const int lane = threadIdx.x & 31;

    // contiguous tile range for this block: tiles [t0, t1)
    const int t0 = (int)(((long long)blockIdx.x * NTILES) / NBLOCKS);
    const int t1 = (int)(((long long)(blockIdx.x + 1) * NTILES) / NBLOCKS);

    for (int t = t0; t < t1; t++) {
        const int b  = t >> 5;                               // 0..127
        const int mb = t & 31;                               // 0..31
        const int m0 = mb * M_PER_BLOCK + warp * M_PER_WARP; // warp's first m

        // x[b] in registers (L1-hit after first touch)
        const float4* __restrict__ xv =
            reinterpret_cast<const float4*>(x + (size_t)b * D);
        const float4 xa0 = xv[lane];
        const float4 xa1 = xv[32 + lane];

        const float4* __restrict__ wv =
            reinterpret_cast<const float4*>(w + (size_t)m0 * D);
        float4* __restrict__ ov =
            reinterpret_cast<float4*>(diffs + ((size_t)b * MAPM + m0) * D);

        float acc[M_PER_WARP];

        // 1-deep software pipeline on the w row
        float4 wn0 = wv[lane];
        float4 wn1 = wv[32 + lane];

#pragma unroll
        for (int i = 0; i < M_PER_WARP; i++) {
            float4 wa0 = wn0, wa1 = wn1;
            if (i + 1 < M_PER_WARP) {
                wn0 = wv[(i + 1) * 64 + lane];        // contiguous next w row
                wn1 = wv[(i + 1) * 64 + 32 + lane];
            }

            float4 d0, d1;
            d0.x = xa0.x - wa0.x;  d0.y = xa0.y - wa0.y;
            d0.z = xa0.z - wa0.z;  d0.w = xa0.w - wa0.w;
            d1.x = xa1.x - wa1.x;  d1.y = xa1.y - wa1.y;
            d1.z = xa1.z - wa1.z;  d1.w = xa1.w - wa1.w;

            // contiguous streaming stores: warp covers 16KB
            __stcs(ov + i * 64 + lane,      d0);
            __stcs(ov + i * 64 + 32 + lane, d1);

            float a;
            a = d0.x * d0.x;
            a = fmaf(d0.y, d0.y, a);
            a = fmaf(d0.z, d0.z, a);
            a = fmaf(d0.w, d0.w, a);
            a = fmaf(d1.x, d1.x, a);
            a = fmaf(d1.y, d1.y, a);
            a = fmaf(d1.z, d1.z, a);
            a = fmaf(d1.w, d1.w, a);
            acc[i] = a;                 // per-lane partial; no cross-lane ops
        }

        // 16 independent warp reductions, interleaved (latency overlapped)
#pragma unroll
        for (int off = 16; off; off >>= 1) {
#pragma unroll
            for (int i = 0; i < M_PER_WARP; i++)
                acc[i] += __shfl_down_sync(0xffffffffu, acc[i], off);
        }

        if (lane == 0) {
            // local argmin over this warp's 16 neurons, then ONE atomic.
            // key = (d2_bits << 32) | m: u64 min == argmin, lowest-m ties.
            unsigned long long best = 0xFFFFFFFFFFFFFFFFULL;
#pragma unroll
            for (int i = 0; i < M_PER_WARP; i++) {
                unsigned long long key =
                    ((unsigned long long)__float_as_uint(acc[i]) << 32) |
                    (unsigned int)(m0 + i);
                best = (key < best) ? key : best;
            }
            atomicMax(&g_best[b], ~best);  // min(key) == max(~key); 0-init safe
        }
    }

    // ---- last-block epilogue: write bmus, re-arm globals for next replay ----
    __shared__ unsigned int s_last;
    __syncthreads();
    if (threadIdx.x == 0) {
        __threadfence();  // publish this block's g_best updates
        unsigned int ticket = atomicAdd(&g_done, 1);
        s_last = (ticket == NBLOCKS - 1) ? 1u : 0u;
    }
    __syncthreads();
    if (s_last) {
        __threadfence();  // acquire all other blocks' g_best updates
        if (threadIdx.x < B) {
            unsigned long long v = ~g_best[threadIdx.x];
            unsigned int mm = (unsigned int)(v & 0xFFFFFFFFu);
            out[threadIdx.x * 2 + 0] = (float)(mm >> 6);   // row
            out[threadIdx.x * 2 + 1] = (float)(mm & 63);   // col
            g_best[threadIdx.x] = 0ULL;                    // re-arm
        }
        if (threadIdx.x == 0) g_done = 0;                  // re-arm ticket
    }
}

extern "C" void kernel_launch(void* const* d_in, const int* in_sizes, int n_in,
                              void* d_out, int out_size) {
    const float* x = (const float*)d_in[0];
    const float* w = (const float*)d_in[1];
    som_fused_kernel<<<NBLOCKS, 256>>>(x, w, (float*)d_out);
}

// round 10
// speedup vs baseline: 1.0804x; 1.0100x over previous
#include <cuda_runtime.h>
#include <cstdint>

// SOM forward: x[128,256] f32, weights[64,64,256] f32
// out = [ bmus(128*2 floats) , diffs(128*64*64*256 floats) ]
//
// R10: R5 champion config (grid 4096 = (b, m-block) in output memory order,
// 256 thr, warp = 16 contiguous m, 16KB contiguous streams, acc[16],
// deferred reductions, 1 atomic/warp) with 256-bit memory ops: lane owns
// 32B of each 1KB row -> ONE ld.global.v8 + ONE st.global.cs.v8 per m
// (half the LDG/STG issue slots of R5). Single launch; last-block epilogue
// writes bmus + re-arms globals (graph-replay deterministic).

#define B 128
#define D 256
#define MAPM 4096                 // 64*64 neurons
#define M_PER_WARP 16
#define WARPS_PER_BLOCK 8
#define M_PER_BLOCK (M_PER_WARP * WARPS_PER_BLOCK)  // 128
#define MBLOCKS (MAPM / M_PER_BLOCK)                // 32
#define NBLOCKS (B * MBLOCKS)                       // 4096

__device__ unsigned long long g_best[B];   // zero-init; holds ~min_key
__device__ unsigned int g_done;            // zero-init ticket

__device__ __forceinline__ void ldg_v8(const float* p, float r[8]) {
    asm volatile(
        "ld.global.v8.f32 {%0,%1,%2,%3,%4,%5,%6,%7}, [%8];"
        : "=f"(r[0]), "=f"(r[1]), "=f"(r[2]), "=f"(r[3]),
          "=f"(r[4]), "=f"(r[5]), "=f"(r[6]), "=f"(r[7])
        : "l"(p));
}

__device__ __forceinline__ void stg_cs_v8(float* p, const float r[8]) {
    asm volatile(
        "st.global.cs.v8.f32 [%0], {%1,%2,%3,%4,%5,%6,%7,%8};"
        :: "l"(p),
           "f"(r[0]), "f"(r[1]), "f"(r[2]), "f"(r[3]),
           "f"(r[4]), "f"(r[5]), "f"(r[6]), "f"(r[7])
        : "memory");
}

__global__ __launch_bounds__(256) void som_fused_kernel(
    const float* __restrict__ x,
    const float* __restrict__ w,
    float* __restrict__ out)   // out = [bmus | diffs]
{
    float* __restrict__ diffs = out + B * 2;

    const int warp = threadIdx.x >> 5;
    const int lane = threadIdx.x & 31;
    const int b    = blockIdx.x >> 5;                       // 0..127
    const int mb   = blockIdx.x & 31;                       // 0..31
    const int m0   = mb * M_PER_BLOCK + warp * M_PER_WARP;  // warp's first m

    // x[b]: lane owns 8 consecutive floats (32B) of the 1KB row
    float xa[8];
    ldg_v8(x + (size_t)b * D + lane * 8, xa);

    const float* __restrict__ wbase = w + (size_t)m0 * D + lane * 8;
    float* __restrict__ obase = diffs + ((size_t)b * MAPM + m0) * D + lane * 8;

    float acc[M_PER_WARP];

    // 1-deep software pipeline on the w row
    float wn[8];
    ldg_v8(wbase, wn);

#pragma unroll
    for (int i = 0; i < M_PER_WARP; i++) {
        float wa[8];
#pragma unroll
        for (int k = 0; k < 8; k++) wa[k] = wn[k];
        if (i + 1 < M_PER_WARP)
            ldg_v8(wbase + (i + 1) * D, wn);   // contiguous next w row

        float d[8];
#pragma unroll
        for (int k = 0; k < 8; k++) d[k] = xa[k] - wa[k];

        // one 256-bit streaming store per m (warp covers 1KB/iter, 16KB total)
        stg_cs_v8(obase + i * D, d);

        float a = d[0] * d[0];
#pragma unroll
        for (int k = 1; k < 8; k++) a = fmaf(d[k], d[k], a);
        acc[i] = a;                    // per-lane partial; no cross-lane ops
    }

    // 16 independent warp reductions, interleaved (latency overlapped)
#pragma unroll
    for (int off = 16; off; off >>= 1) {
#pragma unroll
        for (int i = 0; i < M_PER_WARP; i++)
            acc[i] += __shfl_down_sync(0xffffffffu, acc[i], off);
    }

    if (lane == 0) {
        // local argmin over this warp's 16 neurons, then ONE global atomic.
        // key = (d2_bits << 32) | m: u64 min == argmin with lowest-m ties.
        unsigned long long best = 0xFFFFFFFFFFFFFFFFULL;
#pragma unroll
        for (int i = 0; i < M_PER_WARP; i++) {
            unsigned long long key =
                ((unsigned long long)__float_as_uint(acc[i]) << 32) |
                (unsigned int)(m0 + i);
            best = (key < best) ? key : best;
        }
        atomicMax(&g_best[b], ~best);   // min(key) == max(~key); zero-init safe
    }

    // ---- last-block epilogue: write bmus, re-arm globals for next replay ----
    __shared__ unsigned int s_last;
    __syncthreads();
    if (threadIdx.x == 0) {
        __threadfence();  // publish this block's g_best update
        unsigned int ticket = atomicAdd(&g_done, 1);
        s_last = (ticket == NBLOCKS - 1) ? 1u : 0u;
    }
    __syncthreads();
    if (s_last) {
        __threadfence();  // acquire all other blocks' g_best updates
        if (threadIdx.x < B) {
            unsigned long long v = ~g_best[threadIdx.x];
            unsigned int mm = (unsigned int)(v & 0xFFFFFFFFu);
            out[threadIdx.x * 2 + 0] = (float)(mm >> 6);   // row
            out[threadIdx.x * 2 + 1] = (float)(mm & 63);   // col
            g_best[threadIdx.x] = 0ULL;                    // re-arm
        }
        if (threadIdx.x == 0) g_done = 0;                  // re-arm ticket
    }
}

extern "C" void kernel_launch(void* const* d_in, const int* in_sizes, int n_in,
                              void* d_out, int out_size) {
    const float* x = (const float*)d_in[0];
    const float* w = (const float*)d_in[1];
    som_fused_kernel<<<NBLOCKS, 256>>>(x, w, (float*)d_out);
}

// round 11
// speedup vs baseline: 1.1198x; 1.0365x over previous
#include <cuda_runtime.h>
#include <cstdint>

// SOM forward: x[128,256] f32, weights[64,64,256] f32
// out = [ bmus(128*2 floats) , diffs(128*64*64*256 floats) ]
//
// R11: occupancy push on the R5 champion. Identical decomposition
// (grid 4096 = (b, m-block) in output memory order, 256 thr, warp = 16
// contiguous m, 16KB contiguous __stcs streams, per-lane acc[16], deferred
// interleaved reductions, 1 atomic/warp) with two register cuts:
//  - no w software pipeline (w is L2-resident; extra warps hide latency)
//  - __launch_bounds__(256, 6): cap 42 regs -> 6 blocks/SM (48 warps)
// DRAM% tracked occupancy across R5-R10; more resident store streams
// should lift DRAM active. Single launch; last-block epilogue.

#define B 128
#define D 256
#define MAPM 4096                 // 64*64 neurons
#define M_PER_WARP 16
#define WARPS_PER_BLOCK 8
#define M_PER_BLOCK (M_PER_WARP * WARPS_PER_BLOCK)  // 128
#define MBLOCKS (MAPM / M_PER_BLOCK)                // 32
#define NBLOCKS (B * MBLOCKS)                       // 4096

__device__ unsigned long long g_best[B];   // zero-init; holds ~min_key
__device__ unsigned int g_done;            // zero-init ticket

__global__ __launch_bounds__(256, 6) void som_fused_kernel(
    const float* __restrict__ x,
    const float* __restrict__ w,
    float* __restrict__ out)   // out = [bmus | diffs]
{
    float* __restrict__ diffs = out + B * 2;

    const int warp = threadIdx.x >> 5;
    const int lane = threadIdx.x & 31;
    const int b    = blockIdx.x >> 5;                       // 0..127
    const int mb   = blockIdx.x & 31;                       // 0..31
    const int m0   = mb * M_PER_BLOCK + warp * M_PER_WARP;  // warp's first m

    // x[b] in registers (shared by all 16 neurons)
    const float4* __restrict__ xv = reinterpret_cast<const float4*>(x + (size_t)b * D);
    const float4 xa0 = xv[lane];
    const float4 xa1 = xv[32 + lane];

    const float4* __restrict__ wv =
        reinterpret_cast<const float4*>(w + (size_t)m0 * D);
    float4* __restrict__ ov =
        reinterpret_cast<float4*>(diffs + ((size_t)b * MAPM + m0) * D);

    float acc[M_PER_WARP];

#pragma unroll
    for (int i = 0; i < M_PER_WARP; i++) {
        // direct w loads (L2/L1-resident); no software pipeline -> fewer regs
        float4 wa0 = wv[i * 64 + lane];
        float4 wa1 = wv[i * 64 + 32 + lane];

        float4 d0, d1;
        d0.x = xa0.x - wa0.x;  d0.y = xa0.y - wa0.y;
        d0.z = xa0.z - wa0.z;  d0.w = xa0.w - wa0.w;
        d1.x = xa1.x - wa1.x;  d1.y = xa1.y - wa1.y;
        d1.z = xa1.z - wa1.z;  d1.w = xa1.w - wa1.w;

        // contiguous streaming stores: warp covers [m0*1KB, m0*1KB + 16KB)
        __stcs(ov + i * 64 + lane,      d0);
        __stcs(ov + i * 64 + 32 + lane, d1);

        float a;
        a = d0.x * d0.x;
        a = fmaf(d0.y, d0.y, a);
        a = fmaf(d0.z, d0.z, a);
        a = fmaf(d0.w, d0.w, a);
        a = fmaf(d1.x, d1.x, a);
        a = fmaf(d1.y, d1.y, a);
        a = fmaf(d1.z, d1.z, a);
        a = fmaf(d1.w, d1.w, a);
        acc[i] = a;                    // per-lane partial; no cross-lane ops
    }

    // 16 independent warp reductions, interleaved (latency overlapped)
#pragma unroll
    for (int off = 16; off; off >>= 1) {
#pragma unroll
        for (int i = 0; i < M_PER_WARP; i++)
            acc[i] += __shfl_down_sync(0xffffffffu, acc[i], off);
    }

    if (lane == 0) {
        // local argmin over this warp's 16 neurons, then ONE global atomic.
        // key = (d2_bits << 32) | m: u64 min == argmin with lowest-m ties.
        unsigned long long best = 0xFFFFFFFFFFFFFFFFULL;
#pragma unroll
        for (int i = 0; i < M_PER_WARP; i++) {
            unsigned long long key =
                ((unsigned long long)__float_as_uint(acc[i]) << 32) |
                (unsigned int)(m0 + i);
            best = (key < best) ? key : best;
        }
        atomicMax(&g_best[b], ~best);   // min(key) == max(~key); zero-init safe
    }

    // ---- last-block epilogue: write bmus, re-arm globals for next replay ----
    __shared__ unsigned int s_last;
    __syncthreads();
    if (threadIdx.x == 0) {
        __threadfence();  // publish this block's g_best update
        unsigned int ticket = atomicAdd(&g_done, 1);
        s_last = (ticket == NBLOCKS - 1) ? 1u : 0u;
    }
    __syncthreads();
    if (s_last) {
        __threadfence();  // acquire all other blocks' g_best updates
        if (threadIdx.x < B) {
            unsigned long long v = ~g_best[threadIdx.x];
            unsigned int mm = (unsigned int)(v & 0xFFFFFFFFu);
            out[threadIdx.x * 2 + 0] = (float)(mm >> 6);   // row
            out[threadIdx.x * 2 + 1] = (float)(mm & 63);   // col
            g_best[threadIdx.x] = 0ULL;                    // re-arm
        }
        if (threadIdx.x == 0) g_done = 0;                  // re-arm ticket
    }
}

extern "C" void kernel_launch(void* const* d_in, const int* in_sizes, int n_in,
                              void* d_out, int out_size) {
    const float* x = (const float*)d_in[0];
    const float* w = (const float*)d_in[1];
    som_fused_kernel<<<NBLOCKS, 256>>>(x, w, (float*)d_out);
}

// round 12
// speedup vs baseline: 1.1605x; 1.0363x over previous
#include <cuda_runtime.h>
#include <cstdint>

// SOM forward: x[128,256] f32, weights[64,64,256] f32
// out = [ bmus(128*2 floats) , diffs(128*64*64*256 floats) ]
//
// FINAL (R5 champion, re-confirmed): the kernel is HBM-write-bound at the
// practical write ceiling (~5.45 TB/s, 69% of spec). Design:
//  - block = (batch b, 128 contiguous neurons), grid 4096 in OUTPUT MEMORY
//    ORDER -> concurrent wave writes are packed, maximizing DRAM locality
//  - warp = 16 contiguous m: 16KB contiguous __stcs streaming stores
//  - 1-deep software pipeline on the L2-resident w rows
//  - d2 accumulated per-lane (acc[16]), 16 interleaved deferred shuffle
//    reductions, ONE packed-key atomic per warp (min(key) == max(~key),
//    low bits carry m so ties resolve to the lowest index = argmin)
//  - single launch; last-block epilogue writes bmus and re-arms the
//    __device__ globals so graph replays are deterministic.
// Systematically falsified alternatives (all slower): TMA bulk stores,
// w-reuse across batches, L1-shared w slabs, persistent single-wave grid,
// 256-bit ld/st, higher-occupancy register cuts.

#define B 128
#define D 256
#define MAPM 4096                 // 64*64 neurons
#define M_PER_WARP 16
#define WARPS_PER_BLOCK 8
#define M_PER_BLOCK (M_PER_WARP * WARPS_PER_BLOCK)  // 128
#define MBLOCKS (MAPM / M_PER_BLOCK)                // 32
#define NBLOCKS (B * MBLOCKS)                       // 4096

__device__ unsigned long long g_best[B];   // zero-init; holds ~min_key
__device__ unsigned int g_done;            // zero-init ticket

__global__ __launch_bounds__(256) void som_fused_kernel(
    const float* __restrict__ x,
    const float* __restrict__ w,
    float* __restrict__ out)   // out = [bmus | diffs]
{
    float* __restrict__ diffs = out + B * 2;

    const int warp = threadIdx.x >> 5;
    const int lane = threadIdx.x & 31;
    const int b    = blockIdx.x >> 5;                       // 0..127
    const int mb   = blockIdx.x & 31;                       // 0..31
    const int m0   = mb * M_PER_BLOCK + warp * M_PER_WARP;  // warp's first m

    // x[b] in registers (shared by all 16 neurons)
    const float4* __restrict__ xv = reinterpret_cast<const float4*>(x + (size_t)b * D);
    const float4 xa0 = xv[lane];
    const float4 xa1 = xv[32 + lane];

    const float4* __restrict__ wv =
        reinterpret_cast<const float4*>(w + (size_t)m0 * D);
    float4* __restrict__ ov =
        reinterpret_cast<float4*>(diffs + ((size_t)b * MAPM + m0) * D);

    float acc[M_PER_WARP];

    // 1-deep software pipeline on the w row
    float4 wn0 = wv[lane];
    float4 wn1 = wv[32 + lane];

#pragma unroll
    for (int i = 0; i < M_PER_WARP; i++) {
        float4 wa0 = wn0, wa1 = wn1;
        if (i + 1 < M_PER_WARP) {
            wn0 = wv[(i + 1) * 64 + lane];        // contiguous next w row
            wn1 = wv[(i + 1) * 64 + 32 + lane];
        }

        float4 d0, d1;
        d0.x = xa0.x - wa0.x;  d0.y = xa0.y - wa0.y;
        d0.z = xa0.z - wa0.z;  d0.w = xa0.w - wa0.w;
        d1.x = xa1.x - wa1.x;  d1.y = xa1.y - wa1.y;
        d1.z = xa1.z - wa1.z;  d1.w = xa1.w - wa1.w;

        // contiguous streaming stores: warp covers [m0*1KB, m0*1KB + 16KB)
        __stcs(ov + i * 64 + lane,      d0);
        __stcs(ov + i * 64 + 32 + lane, d1);

        float a;
        a = d0.x * d0.x;
        a = fmaf(d0.y, d0.y, a);
        a = fmaf(d0.z, d0.z, a);
        a = fmaf(d0.w, d0.w, a);
        a = fmaf(d1.x, d1.x, a);
        a = fmaf(d1.y, d1.y, a);
        a = fmaf(d1.z, d1.z, a);
        a = fmaf(d1.w, d1.w, a);
        acc[i] = a;                    // per-lane partial; no cross-lane ops
    }

    // 16 independent warp reductions, interleaved (latency overlapped)
#pragma unroll
    for (int off = 16; off; off >>= 1) {
#pragma unroll
        for (int i = 0; i < M_PER_WARP; i++)
            acc[i] += __shfl_down_sync(0xffffffffu, acc[i], off);
    }

    if (lane == 0) {
        // local argmin over this warp's 16 neurons, then ONE global atomic.
        // key = (d2_bits << 32) | m: u64 min == argmin with lowest-m ties.
        unsigned long long best = 0xFFFFFFFFFFFFFFFFULL;
#pragma unroll
        for (int i = 0; i < M_PER_WARP; i++) {
            unsigned long long key =
                ((unsigned long long)__float_as_uint(acc[i]) << 32) |
                (unsigned int)(m0 + i);
            best = (key < best) ? key : best;
        }
        atomicMax(&g_best[b], ~best);   // min(key) == max(~key); zero-init safe
    }

    // ---- last-block epilogue: write bmus, re-arm globals for next replay ----
    __shared__ unsigned int s_last;
    __syncthreads();
    if (threadIdx.x == 0) {
        __threadfence();  // publish this block's g_best update
        unsigned int ticket = atomicAdd(&g_done, 1);
        s_last = (ticket == NBLOCKS - 1) ? 1u : 0u;
    }
    __syncthreads();
    if (s_last) {
        __threadfence();  // acquire all other blocks' g_best updates
        if (threadIdx.x < B) {
            unsigned long long v = ~g_best[threadIdx.x];
            unsigned int mm = (unsigned int)(v & 0xFFFFFFFFu);
            out[threadIdx.x * 2 + 0] = (float)(mm >> 6);   // row
            out[threadIdx.x * 2 + 1] = (float)(mm & 63);   // col
            g_best[threadIdx.x] = 0ULL;                    // re-arm
        }
        if (threadIdx.x == 0) g_done = 0;                  // re-arm ticket
    }
}

extern "C" void kernel_launch(void* const* d_in, const int* in_sizes, int n_in,
                              void* d_out, int out_size) {
    const float* x = (const float*)d_in[0];
    const float* w = (const float*)d_in[1];
    som_fused_kernel<<<NBLOCKS, 256>>>(x, w, (float*)d_out);
}